// round 4
// baseline (speedup 1.0000x reference)
#include <cuda_runtime.h>
#include <math.h>
#include <stdint.h>

// Problem constants
#define BB 4
#define SS 2048
#define EE 1024
#define HH 8
#define DD 128
#define TT (BB*SS)          // 8192 tokens
#define EPSF 1e-5f

// ---------------- scratch (device globals; no allocations allowed) ----------
__device__ float g_Z  [TT*EE];     // tanh(x@W_ez)          [t][h*128+d]
__device__ float g_ST [TT*EE];     // scan states
__device__ float g_HLN[TT*EE];     // LN(states*os_diag)
__device__ float g_H1 [TT*EE];     // gelu FFN hidden
__device__ float g_P  [TT*EE];     // pre-LN output
__device__ float g_LG [TT*HH];     // logits
__device__ float g_SC [TT*HH];     // softmax scores
__device__ float g_V  [HH*DD];     // W2[h] @ w_att
__device__ float g_C  [HH];        // b2[h] . w_att
__device__ float g_WezT[EE*EE];    // W_ez transposed  [n][k]
__device__ float g_W2T [EE*EE];    // ff_W2 transposed [n][k]
__device__ float g_XP  [TT*EE*2];  // packed hi/lo x
__device__ float g_GP  [TT*EE*2];  // packed hi/lo g (score-scaled h1)
__device__ float g_WezTP[EE*EE*2]; // packed hi/lo W_ez^T
__device__ float g_W2TP [EE*EE*2]; // packed hi/lo W2^T

// ---------------- helpers ----------------------------------------------------
__device__ __forceinline__ uint32_t f2tf(float x) {
    uint32_t u;
    asm("cvt.rna.tf32.f32 %0, %1;" : "=r"(u) : "f"(x));
    return u;
}
__device__ __forceinline__ uint32_t smem_u32(const void* p) {
    uint32_t a;
    asm("{ .reg .u64 t; cvta.to.shared.u64 t, %1; cvt.u32.u64 %0, t; }"
        : "=r"(a) : "l"(p));
    return a;
}
#define CP_ASYNC16(dst, src) \
    asm volatile("cp.async.cg.shared.global [%0], [%1], 16;" :: "r"(dst), "l"(src) : "memory")
#define CP_COMMIT asm volatile("cp.async.commit_group;" ::: "memory")
#define CP_WAIT1  asm volatile("cp.async.wait_group 1;" ::: "memory")

__device__ __forceinline__ void mma8f(float* c,
    float a0, float a1, float a2, float a3, float b0, float b1) {
    asm volatile("mma.sync.aligned.m16n8k8.row.col.f32.tf32.tf32.f32 "
        "{%0,%1,%2,%3}, {%4,%5,%6,%7}, {%8,%9}, {%0,%1,%2,%3};"
        : "+f"(c[0]), "+f"(c[1]), "+f"(c[2]), "+f"(c[3])
        : "r"(__float_as_uint(a0)), "r"(__float_as_uint(a1)),
          "r"(__float_as_uint(a2)), "r"(__float_as_uint(a3)),
          "r"(__float_as_uint(b0)), "r"(__float_as_uint(b1)));
}

// split 8 consecutive k's (a = k0..3, b = k4..7) into 4 packed 16B groups:
// group j = { hi(a[j]), hi(b[j]), lo(a[j]), lo(b[j]) }
__device__ __forceinline__ void pack8(float4 a, float4 b, float* __restrict__ d)
{
    float ha[4], hb[4], la[4], lb[4];
    const float av[4] = {a.x, a.y, a.z, a.w};
    const float bv[4] = {b.x, b.y, b.z, b.w};
    #pragma unroll
    for (int j = 0; j < 4; j++) {
        ha[j] = __uint_as_float(f2tf(av[j]));
        hb[j] = __uint_as_float(f2tf(bv[j]));
        la[j] = __uint_as_float(f2tf(av[j] - ha[j]));
        lb[j] = __uint_as_float(f2tf(bv[j] - hb[j]));
    }
    #pragma unroll
    for (int j = 0; j < 4; j++) {
        float4 g; g.x = ha[j]; g.y = hb[j]; g.z = la[j]; g.w = lb[j];
        ((float4*)d)[j] = g;
    }
}

// ---------------- pack_split: src row-major [rows][1024] -> packed ----------
__global__ void pack_split(const float* __restrict__ src, float* __restrict__ dst)
{
    const int idx = blockIdx.x*256 + threadIdx.x;   // one 8-k chunk
    const float4 a = *(const float4*)(src + (size_t)idx*8);
    const float4 b = *(const float4*)(src + (size_t)idx*8 + 4);
    pack8(a, b, dst + (size_t)idx*16);
}

// ---------------- transpose 1024x1024 ---------------------------------------
__global__ void transpose1024(const float* __restrict__ in, float* __restrict__ out)
{
    __shared__ float tile[32][33];
    const int x = blockIdx.x*32 + threadIdx.x;
    const int y = blockIdx.y*32 + threadIdx.y;
    #pragma unroll
    for (int j = 0; j < 32; j += 8)
        tile[threadIdx.y + j][threadIdx.x] = in[(size_t)(y + j)*EE + x];
    __syncthreads();
    const int x2 = blockIdx.y*32 + threadIdx.x;
    const int y2 = blockIdx.x*32 + threadIdx.y;
    #pragma unroll
    for (int j = 0; j < 32; j += 8)
        out[(size_t)(y2 + j)*EE + x2] = tile[threadIdx.x][threadIdx.y + j];
}

// ---------------- prep_v -----------------------------------------------------
__global__ void prep_v(const float* __restrict__ W2,
                       const float* __restrict__ b2,
                       const float* __restrict__ watt)
{
    int hh = blockIdx.x;
    int d  = threadIdx.x;
    const float* row = W2 + ((size_t)hh*DD + d)*EE;
    float a0=0.f,a1=0.f,a2=0.f,a3=0.f;
    for (int e = 0; e < EE; e += 4) {
        a0 = fmaf(row[e+0], watt[e+0], a0);
        a1 = fmaf(row[e+1], watt[e+1], a1);
        a2 = fmaf(row[e+2], watt[e+2], a2);
        a3 = fmaf(row[e+3], watt[e+3], a3);
    }
    g_V[hh*DD + d] = (a0+a1)+(a2+a3);
    if (d == 0) {
        const float* br = b2 + (size_t)hh*EE;
        float c0=0.f;
        for (int e = 0; e < EE; e++) c0 = fmaf(br[e], watt[e], c0);
        g_C[hh] = c0;
    }
}

// ======= mma.sync tf32 3-pass GEMM on pre-split packed operands ==============
// Apk [8192 rows][2048]: packed row (k-chunks of 8, 4 groups of 16B each).
// Bpk [1024 rows][2048]: packed W^T rows.
// CTA 128x128, 8 warps (2m x 4n), warp tile 64x32, K per stage = 16.
// cp.async 3-stage pipeline; XOR-swizzled smem, LDS.128 fragment loads.
// EPI==0: g_Z = tanh(v + bias[c]); EPI==2: g_P = v + sum_h g_SC[r][h]*bias[h*1024+c]
template<int EPI>
__global__ void __launch_bounds__(256) mma_gemm2(
    const float* __restrict__ Apk, const float* __restrict__ Bpk,
    const float* __restrict__ bias)
{
    extern __shared__ float smq[];      // 3 stages x 8192 floats (A 4096 + B 4096)
    float* C = (EPI==0) ? g_Z : g_P;

    const int tid  = threadIdx.x;
    const int wid  = tid >> 5;
    const int lane = tid & 31;
    const int wm   = wid >> 2;          // 0..1
    const int wn   = wid & 3;           // 0..3
    const int r    = lane >> 2;         // 0..7
    const int cq   = lane & 3;          // 0..3
    const int xr   = ((r & 1) << 2) | ((r >> 1) & 3);

    const int m0 = blockIdx.y * 128;
    const int n0 = blockIdx.x * 128;

    // producer mapping: thread -> (row, half); 4 x 16B groups per matrix per stage
    const int prow  = tid & 127;
    const int phalf = tid >> 7;
    const int pxw   = ((prow & 1) << 2) | ((prow >> 1) & 3);
    const uint32_t smb = smem_u32(smq);
    const float* srcA = Apk + (size_t)(m0 + prow)*2048 + phalf*16;
    const float* srcB = Bpk + (size_t)(n0 + prow)*2048 + phalf*16;
    uint32_t dA[4], dB[4];
    #pragma unroll
    for (int i = 0; i < 4; i++) {
        const uint32_t gp = (uint32_t)(((phalf*4 + i) ^ pxw) * 16);
        dA[i] = smb + prow*128 + gp;
        dB[i] = smb + 16384u + prow*128 + gp;
    }

    #define ISSUE(kt, st) do {                                   \
        const uint32_t _so = (uint32_t)(st) * 32768u;            \
        const float* _sa = srcA + (kt)*32;                       \
        const float* _sb = srcB + (kt)*32;                       \
        _Pragma("unroll")                                        \
        for (int _i = 0; _i < 4; _i++) {                         \
            CP_ASYNC16(dA[_i] + _so, _sa + _i*4);                \
            CP_ASYNC16(dB[_i] + _so, _sb + _i*4);                \
        } } while (0)

    ISSUE(0, 0); CP_COMMIT;
    ISSUE(1, 1); CP_COMMIT;

    float acc[4][4][4];
    #pragma unroll
    for (int i = 0; i < 4; i++)
        #pragma unroll
        for (int j = 0; j < 4; j++)
            #pragma unroll
            for (int q = 0; q < 4; q++) acc[i][j][q] = 0.f;

    const int NKT = 64;
    #pragma unroll 1
    for (int kt = 0; kt < NKT; kt++) {
        CP_WAIT1;
        __syncthreads();
        if (kt + 2 < NKT) { ISSUE(kt + 2, (kt + 2) % 3); }
        CP_COMMIT;

        const float* sA = smq + (kt % 3) * 8192;
        const float* sB = sA + 4096;

        #pragma unroll
        for (int s = 0; s < 2; s++) {
            const int go = ((s*4 + cq) ^ xr) * 4;
            float4 bw[4], a0w[4], a1w[4];
            #pragma unroll
            for (int ni = 0; ni < 4; ni++)
                bw[ni] = *(const float4*)(sB + (wn*32 + ni*8 + r)*32 + go);
            #pragma unroll
            for (int mi = 0; mi < 4; mi++) {
                a0w[mi] = *(const float4*)(sA + (wm*64 + mi*16 + r)*32 + go);
                a1w[mi] = *(const float4*)(sA + (wm*64 + mi*16 + 8 + r)*32 + go);
            }
            // pass 1: hi * hi
            #pragma unroll
            for (int mi = 0; mi < 4; mi++)
                #pragma unroll
                for (int ni = 0; ni < 4; ni++)
                    mma8f(acc[mi][ni], a0w[mi].x, a1w[mi].x, a0w[mi].y, a1w[mi].y,
                          bw[ni].x, bw[ni].y);
            // pass 2: lo * hi
            #pragma unroll
            for (int mi = 0; mi < 4; mi++)
                #pragma unroll
                for (int ni = 0; ni < 4; ni++)
                    mma8f(acc[mi][ni], a0w[mi].z, a1w[mi].z, a0w[mi].w, a1w[mi].w,
                          bw[ni].x, bw[ni].y);
            // pass 3: hi * lo
            #pragma unroll
            for (int mi = 0; mi < 4; mi++)
                #pragma unroll
                for (int ni = 0; ni < 4; ni++)
                    mma8f(acc[mi][ni], a0w[mi].x, a1w[mi].x, a0w[mi].y, a1w[mi].y,
                          bw[ni].z, bw[ni].w);
        }
    }
    #undef ISSUE

    // ---------------- epilogue ----------------
    #pragma unroll
    for (int mi = 0; mi < 4; mi++) {
        const int row0 = m0 + wm*64 + mi*16 + r;    // and row0+8
        float sAr[8], sBr[8];
        if (EPI == 2) {
            #pragma unroll
            for (int h2 = 0; h2 < 8; h2++) {
                sAr[h2] = g_SC[(size_t)row0*8 + h2];
                sBr[h2] = g_SC[(size_t)(row0+8)*8 + h2];
            }
        }
        #pragma unroll
        for (int ni = 0; ni < 4; ni++) {
            const int col = n0 + wn*32 + ni*8 + 2*cq;
            float v0 = acc[mi][ni][0], v1 = acc[mi][ni][1];
            float v2 = acc[mi][ni][2], v3 = acc[mi][ni][3];
            if (EPI == 0) {
                v0 = tanhf(v0 + bias[col]);
                v1 = tanhf(v1 + bias[col+1]);
                v2 = tanhf(v2 + bias[col]);
                v3 = tanhf(v3 + bias[col+1]);
            } else {
                float b00=0.f, b01=0.f, b10=0.f, b11=0.f;
                #pragma unroll
                for (int h2 = 0; h2 < 8; h2++) {
                    const float w0 = bias[(size_t)h2*EE + col];
                    const float w1 = bias[(size_t)h2*EE + col + 1];
                    b00 = fmaf(sAr[h2], w0, b00);
                    b01 = fmaf(sAr[h2], w1, b01);
                    b10 = fmaf(sBr[h2], w0, b10);
                    b11 = fmaf(sBr[h2], w1, b11);
                }
                v0 += b00; v1 += b01; v2 += b10; v3 += b11;
            }
            float2 p0; p0.x = v0; p0.y = v1;
            float2 p1; p1.x = v2; p1.y = v3;
            *(float2*)(C + (size_t)row0*EE + col)     = p0;
            *(float2*)(C + (size_t)(row0+8)*EE + col) = p1;
        }
    }
}

// ---------------- SIMT 128x128 GEMM for per-head FFN ------------------------
__global__ void __launch_bounds__(256, 2) gemm_ffn(
    const float* __restrict__ Bm, const float* __restrict__ bias)
{
    const float* A = g_HLN;
    float*       C = g_H1;

    __shared__ float As[2][8][128];
    __shared__ float Bs[2][8][128];

    const int tid = threadIdx.x;
    const int by  = blockIdx.y;
    const int h   = blockIdx.z;

    const int tx = tid & 15;
    const int ty = tid >> 4;
    const int arow = tid >> 1;
    const int ac4  = (tid & 1) * 4;
    const int brow = tid >> 5;
    const int bc4  = (tid & 31) * 4;

    const float* Ag = A + (size_t)h*DD + (size_t)(by*128 + arow)*1024 + ac4;
    const float* Bg = Bm + (size_t)h*DD*DD + (size_t)brow*DD + bc4;

    float4 ar = *(const float4*)Ag;
    float4 br = *(const float4*)Bg;

    As[0][ac4+0][arow] = ar.x;
    As[0][ac4+1][arow] = ar.y;
    As[0][ac4+2][arow] = ar.z;
    As[0][ac4+3][arow] = ar.w;
    *(float4*)&Bs[0][brow][bc4] = br;
    __syncthreads();

    float acc[8][8];
    #pragma unroll
    for (int i = 0; i < 8; i++)
        #pragma unroll
        for (int j = 0; j < 8; j++) acc[i][j] = 0.f;

    const int nk = DD >> 3;   // 16
    for (int kt = 0; kt < nk; kt++) {
        const int cur = kt & 1;
        const int nxt = cur ^ 1;
        if (kt + 1 < nk) {
            ar = *(const float4*)(Ag + (size_t)(kt+1)*8);
            br = *(const float4*)(Bg + (size_t)(kt+1)*8*DD);
        }
        #pragma unroll
        for (int k = 0; k < 8; k++) {
            float a[8], b[8];
            *(float4*)(a)   = *(float4*)&As[cur][k][ty*8];
            *(float4*)(a+4) = *(float4*)&As[cur][k][ty*8+4];
            *(float4*)(b)   = *(float4*)&Bs[cur][k][tx*8];
            *(float4*)(b+4) = *(float4*)&Bs[cur][k][tx*8+4];
            #pragma unroll
            for (int i = 0; i < 8; i++)
                #pragma unroll
                for (int j = 0; j < 8; j++)
                    acc[i][j] = fmaf(a[i], b[j], acc[i][j]);
        }
        if (kt + 1 < nk) {
            As[nxt][ac4+0][arow] = ar.x;
            As[nxt][ac4+1][arow] = ar.y;
            As[nxt][ac4+2][arow] = ar.z;
            As[nxt][ac4+3][arow] = ar.w;
            *(float4*)&Bs[nxt][brow][bc4] = br;
        }
        __syncthreads();
    }

    const int colBase = h*DD;
    const int rBase   = by*128 + ty*8;
    #pragma unroll
    for (int i = 0; i < 8; i++) {
        const int r = rBase + i;
        float logit = 0.f;
        #pragma unroll
        for (int j = 0; j < 8; j++) {
            const int c = colBase + tx*8 + j;
            float v = acc[i][j] + bias[c];
            v = 0.5f * v * (1.f + erff(v * 0.70710678118654752f));
            logit = fmaf(v, g_V[c], logit);
            C[(size_t)r*1024 + c] = v;
        }
        #pragma unroll
        for (int off = 8; off >= 1; off >>= 1)
            logit += __shfl_xor_sync(0xffffffffu, logit, off);
        if (tx == 0) g_LG[(size_t)r*8 + h] = logit + g_C[h];
    }
}

// ---------------- sequential gated scan + per-step LN -----------------------
__global__ void scan_kernel(const float* __restrict__ Uh,
                            const float* __restrict__ Uz,
                            const float* __restrict__ Bu,
                            const float* __restrict__ Lg,
                            const float* __restrict__ Lb)
{
    const int bidx = blockIdx.x;
    const int b  = bidx >> 3;
    const int hh = bidx & 7;
    const int lane = threadIdx.x;

    float uh[4], uz[4], bu[4], lg[4], lb[4], h[4];
    #pragma unroll
    for (int i = 0; i < 4; i++) {
        const int d = lane + 32*i;
        uh[i] = Uh[(size_t)hh*DD*DD + (size_t)d*(DD+1)];
        uz[i] = Uz[(size_t)hh*DD*DD + (size_t)d*(DD+1)];
        bu[i] = Bu[hh*DD + d];
        lg[i] = Lg[d];
        lb[i] = Lb[d];
        h[i]  = 0.f;
    }

    const float* zp = g_Z  + (size_t)b*SS*EE + hh*DD + lane;
    float*       sp = g_ST + (size_t)b*SS*EE + hh*DD + lane;

    float z0[4], z1[4];
    #pragma unroll
    for (int i = 0; i < 4; i++) z0[i] = zp[32*i];
    #pragma unroll
    for (int i = 0; i < 4; i++) z1[i] = zp[1024 + 32*i];

    for (int s = 0; s < SS; s++) {
        float z2[4] = {0.f, 0.f, 0.f, 0.f};
        if (s + 2 < SS) {
            const float* p = zp + (size_t)(s+2)*EE;
            #pragma unroll
            for (int i = 0; i < 4; i++) z2[i] = p[32*i];
        }
        float hn[4];
        float s1 = 0.f, s2 = 0.f;
        #pragma unroll
        for (int i = 0; i < 4; i++) {
            float t = fmaf(h[i], uh[i], fmaf(z0[i], uz[i], bu[i]));
            float u = __fdividef(1.f, 1.f + __expf(-t));
            float v = fmaf(u, h[i] - z0[i], z0[i]);
            hn[i] = v;
            s1 += v;
            s2 = fmaf(v, v, s2);
        }
        #pragma unroll
        for (int off = 16; off >= 1; off >>= 1) {
            s1 += __shfl_xor_sync(0xffffffffu, s1, off);
            s2 += __shfl_xor_sync(0xffffffffu, s2, off);
        }
        const float mean = s1 * (1.f/128.f);
        const float var  = fmaf(s2, 1.f/128.f, -mean*mean);
        const float rstd = rsqrtf(var + EPSF);
        float* so = sp + (size_t)s*EE;
        #pragma unroll
        for (int i = 0; i < 4; i++) {
            float o = fmaf((hn[i] - mean) * rstd, lg[i], lb[i]);
            h[i] = o;
            so[32*i] = o;
        }
        #pragma unroll
        for (int i = 0; i < 4; i++) { z0[i] = z1[i]; z1[i] = z2[i]; }
    }
}

// ---------------- head_ln ----------------------------------------------------
__global__ void head_ln(const float* __restrict__ OS,
                        const float* __restrict__ fg,
                        const float* __restrict__ fb)
{
    const int r    = blockIdx.x*8 + (threadIdx.x >> 5);
    const int lane = threadIdx.x & 31;
    const int hh   = r & 7;

    const float4 v = ((const float4*)(g_ST + (size_t)r*128))[lane];
    const int d0 = lane*4;
    const float* osb = OS + (size_t)hh*DD*DD;
    const float o0 = osb[(size_t)(d0+0)*(DD+1)];
    const float o1 = osb[(size_t)(d0+1)*(DD+1)];
    const float o2 = osb[(size_t)(d0+2)*(DD+1)];
    const float o3 = osb[(size_t)(d0+3)*(DD+1)];
    const float y0 = v.x*o0, y1 = v.y*o1, y2 = v.z*o2, y3 = v.w*o3;

    float s1 = (y0+y1)+(y2+y3);
    float s2 = fmaf(y0,y0, fmaf(y1,y1, fmaf(y2,y2, y3*y3)));
    #pragma unroll
    for (int off = 16; off >= 1; off >>= 1) {
        s1 += __shfl_xor_sync(0xffffffffu, s1, off);
        s2 += __shfl_xor_sync(0xffffffffu, s2, off);
    }
    const float mean = s1 * (1.f/128.f);
    const float var  = fmaf(s2, 1.f/128.f, -mean*mean);
    const float rstd = rsqrtf(var + EPSF);

    const float4 gv = ((const float4*)(fg + hh*128))[lane];
    const float4 bv = ((const float4*)(fb + hh*128))[lane];
    float4 o;
    o.x = fmaf((y0-mean)*rstd, gv.x, bv.x);
    o.y = fmaf((y1-mean)*rstd, gv.y, bv.y);
    o.z = fmaf((y2-mean)*rstd, gv.z, bv.z);
    o.w = fmaf((y3-mean)*rstd, gv.w, bv.w);
    ((float4*)(g_HLN + (size_t)r*128))[lane] = o;
}

// ---------------- softmax over heads; emit PACKED g = score*h1 --------------
__global__ void softmax_scale()
{
    const int t    = blockIdx.x*8 + (threadIdx.x >> 5);
    const int lane = threadIdx.x & 31;

    float l[8];
    #pragma unroll
    for (int h2 = 0; h2 < 8; h2++) l[h2] = g_LG[(size_t)t*8 + h2];
    float m = l[0];
    #pragma unroll
    for (int h2 = 1; h2 < 8; h2++) m = fmaxf(m, l[h2]);
    float ssum = 0.f;
    #pragma unroll
    for (int h2 = 0; h2 < 8; h2++) { l[h2] = __expf(l[h2]-m); ssum += l[h2]; }
    const float inv = __fdividef(1.f, ssum);

    const float4* in = (const float4*)(g_H1 + (size_t)t*1024);
    float* gp = g_GP + (size_t)t*2048;
    #pragma unroll
    for (int c = 0; c < 4; c++) {
        const int kc = c*32 + lane;            // chunk of 8 elements
        const float sh = l[kc >> 4] * inv;     // head = (kc*8)>>7
        float4 a = in[kc*2];
        float4 b = in[kc*2 + 1];
        a.x *= sh; a.y *= sh; a.z *= sh; a.w *= sh;
        b.x *= sh; b.y *= sh; b.z *= sh; b.w *= sh;
        pack8(a, b, gp + (size_t)kc*16);
    }
    if (lane < 8) g_SC[(size_t)t*8 + lane] = l[lane]*inv;
}

// ---------------- final LN over E -------------------------------------------
__global__ void final_ln(const float* __restrict__ lg_,
                         const float* __restrict__ lb_,
                         float* __restrict__ out)
{
    __shared__ float sm[16];
    const int t   = blockIdx.x;
    const int tid = threadIdx.x;

    const float4 v = ((const float4*)(g_P + (size_t)t*1024))[tid];
    float s1 = (v.x+v.y)+(v.z+v.w);
    float s2 = fmaf(v.x,v.x, fmaf(v.y,v.y, fmaf(v.z,v.z, v.w*v.w)));
    #pragma unroll
    for (int off = 16; off >= 1; off >>= 1) {
        s1 += __shfl_xor_sync(0xffffffffu, s1, off);
        s2 += __shfl_xor_sync(0xffffffffu, s2, off);
    }
    const int w = tid >> 5, lane = tid & 31;
    if (lane == 0) { sm[w] = s1; sm[8+w] = s2; }
    __syncthreads();
    float t1 = 0.f, t2 = 0.f;
    #pragma unroll
    for (int w2 = 0; w2 < 8; w2++) { t1 += sm[w2]; t2 += sm[8+w2]; }
    const float mean = t1 * (1.f/1024.f);
    const float var  = fmaf(t2, 1.f/1024.f, -mean*mean);
    const float rstd = rsqrtf(var + EPSF);

    const float4 g4 = ((const float4*)lg_)[tid];
    const float4 b4 = ((const float4*)lb_)[tid];
    float4 o;
    o.x = fmaf((v.x-mean)*rstd, g4.x, b4.x);
    o.y = fmaf((v.y-mean)*rstd, g4.y, b4.y);
    o.z = fmaf((v.z-mean)*rstd, g4.z, b4.z);
    o.w = fmaf((v.w-mean)*rstd, g4.w, b4.w);
    ((float4*)(out + (size_t)t*1024))[tid] = o;
}

// ---------------- launch ----------------------------------------------------
#define GEMM_SMEM (3 * 8192 * 4)   // 98304 bytes

extern "C" void kernel_launch(void* const* d_in, const int* in_sizes, int n_in,
                              void* d_out, int out_size)
{
    const float* x      = (const float*)d_in[0];
    const float* W_ez   = (const float*)d_in[1];
    const float* b_ez   = (const float*)d_in[2];
    const float* U_h    = (const float*)d_in[3];
    const float* U_z    = (const float*)d_in[4];
    const float* b_u    = (const float*)d_in[5];
    const float* out_sh = (const float*)d_in[6];
    const float* lns_g  = (const float*)d_in[7];
    const float* lns_b  = (const float*)d_in[8];
    const float* ffln_g = (const float*)d_in[9];
    const float* ffln_b = (const float*)d_in[10];
    const float* ff_W1  = (const float*)d_in[11];
    const float* ff_b1  = (const float*)d_in[12];
    const float* ff_W2  = (const float*)d_in[13];
    const float* ff_b2  = (const float*)d_in[14];
    const float* w_att  = (const float*)d_in[15];
    // d_in[16] = b_att: cancels in softmax
    const float* lno_g  = (const float*)d_in[17];
    const float* lno_b  = (const float*)d_in[18];
    float* out = (float*)d_out;

    static int attr_done = 0;
    cudaFuncSetAttribute(mma_gemm2<0>, cudaFuncAttributeMaxDynamicSharedMemorySize, GEMM_SMEM);
    cudaFuncSetAttribute(mma_gemm2<2>, cudaFuncAttributeMaxDynamicSharedMemorySize, GEMM_SMEM);
    (void)attr_done;

    float* wezT;  cudaGetSymbolAddress((void**)&wezT,  g_WezT);
    float* w2T;   cudaGetSymbolAddress((void**)&w2T,   g_W2T);
    float* wezTP; cudaGetSymbolAddress((void**)&wezTP, g_WezTP);
    float* w2TP;  cudaGetSymbolAddress((void**)&w2TP,  g_W2TP);
    float* xP;    cudaGetSymbolAddress((void**)&xP,    g_XP);
    float* gP;    cudaGetSymbolAddress((void**)&gP,    g_GP);

    // prep: transpose + pre-split weights, pre-split x
    transpose1024<<<dim3(32,32), dim3(32,8)>>>(W_ez, wezT);
    transpose1024<<<dim3(32,32), dim3(32,8)>>>(ff_W2, w2T);
    pack_split<<<EE*EE/8/256, 256>>>(wezT, wezTP);
    pack_split<<<EE*EE/8/256, 256>>>(w2T, w2TP);
    pack_split<<<TT*EE/8/256, 256>>>(x, xP);
    prep_v<<<HH, DD>>>(ff_W2, ff_b2, w_att);

    // z = tanh(x @ W_ez + b_ez)
    mma_gemm2<0><<<dim3(EE/128, TT/128), 256, GEMM_SMEM>>>(xP, wezTP, b_ez);

    // sequential gated scan with per-step LN
    scan_kernel<<<BB*HH, 32>>>(U_h, U_z, b_u, lns_g, lns_b);

    // hln = LN(states * os_diag)
    head_ln<<<TT*HH/8, 256>>>(out_sh, ffln_g, ffln_b);

    // h1 = gelu(hln @ W1[h] + b1[h]); logits in epilogue
    gemm_ffn<<<dim3(1, TT/128, HH), 256>>>(ff_W1, ff_b1);

    // softmax over heads; packed g = score * h1
    softmax_scale<<<TT/8, 256>>>();

    // weighted = g @ W2 + sum_h s_h*b2
    mma_gemm2<2><<<dim3(EE/128, TT/128), 256, GEMM_SMEM>>>(gP, w2TP, ff_b2);

    // final LN -> output
    final_ln<<<TT, 256>>>(lno_g, lno_b, out);
}

// round 5
// speedup vs baseline: 1.7528x; 1.7528x over previous
#include <cuda_runtime.h>
#include <cuda_bf16.h>
#include <math.h>
#include <stdint.h>

// Problem constants
#define BB 4
#define SS 2048
#define EE 1024
#define HH 8
#define DD 128
#define TT (BB*SS)          // 8192 tokens
#define EPSF 1e-5f

// ---------------- scratch (device globals; no allocations allowed) ----------
__device__ float g_Z  [TT*EE];   // tanh(x@W_ez)          [t][h*128+d]
__device__ float g_ST [TT*EE];   // scan states
__device__ float g_HLN[TT*EE];   // LN(states*os_diag)
__device__ float g_H1 [TT*EE];   // gelu FFN hidden
__device__ float g_G  [TT*EE];   // score-scaled h1
__device__ float g_P  [TT*EE];   // pre-LN output
__device__ float g_LG [TT*HH];   // logits
__device__ float g_SC [TT*HH];   // softmax scores
__device__ float g_V  [HH*DD];   // W2[h] @ w_att
__device__ float g_C  [HH];      // b2[h] . w_att
__device__ float g_WezT[EE*EE];  // W_ez transposed  [n][k]
__device__ float g_W2T [EE*EE];  // ff_W2 transposed [n][k]

// ---------------- helpers ----------------------------------------------------
__device__ __forceinline__ uint32_t smem_u32(const void* p) {
    uint32_t a;
    asm("{ .reg .u64 t; cvta.to.shared.u64 t, %1; cvt.u32.u64 %0, t; }"
        : "=r"(a) : "l"(p));
    return a;
}

#define LDSM4(r0, r1, r2, r3, a) \
    asm volatile("ldmatrix.sync.aligned.m8n8.x4.shared.b16 {%0,%1,%2,%3}, [%4];" \
        : "=r"(r0), "=r"(r1), "=r"(r2), "=r"(r3) : "r"(a))
#define LDSM2(r0, r1, a) \
    asm volatile("ldmatrix.sync.aligned.m8n8.x2.shared.b16 {%0,%1}, [%2];" \
        : "=r"(r0), "=r"(r1) : "r"(a))

__device__ __forceinline__ void mmabf(float* c, const uint32_t* a, const uint32_t* b) {
    asm volatile("mma.sync.aligned.m16n8k16.row.col.f32.bf16.bf16.f32 "
        "{%0,%1,%2,%3}, {%4,%5,%6,%7}, {%8,%9}, {%0,%1,%2,%3};"
        : "+f"(c[0]), "+f"(c[1]), "+f"(c[2]), "+f"(c[3])
        : "r"(a[0]), "r"(a[1]), "r"(a[2]), "r"(a[3]), "r"(b[0]), "r"(b[1]));
}

// split 8 fp32 (k0..7) into hi (truncated bf16) and mid (bf16 of residual),
// both packed bf16x2 with even k in the low half; store as one 16B group each.
__device__ __forceinline__ void split_store8(float4 u, float4 v,
                                             char* hiP, char* miP)
{
    const uint32_t e0 = __float_as_uint(u.x), e1 = __float_as_uint(u.y);
    const uint32_t e2 = __float_as_uint(u.z), e3 = __float_as_uint(u.w);
    const uint32_t e4 = __float_as_uint(v.x), e5 = __float_as_uint(v.y);
    const uint32_t e6 = __float_as_uint(v.z), e7 = __float_as_uint(v.w);

    uint4 hi;
    hi.x = __byte_perm(e0, e1, 0x7632);
    hi.y = __byte_perm(e2, e3, 0x7632);
    hi.z = __byte_perm(e4, e5, 0x7632);
    hi.w = __byte_perm(e6, e7, 0x7632);

    const float m0 = u.x - __uint_as_float(e0 & 0xFFFF0000u);
    const float m1 = u.y - __uint_as_float(e1 & 0xFFFF0000u);
    const float m2 = u.z - __uint_as_float(e2 & 0xFFFF0000u);
    const float m3 = u.w - __uint_as_float(e3 & 0xFFFF0000u);
    const float m4 = v.x - __uint_as_float(e4 & 0xFFFF0000u);
    const float m5 = v.y - __uint_as_float(e5 & 0xFFFF0000u);
    const float m6 = v.z - __uint_as_float(e6 & 0xFFFF0000u);
    const float m7 = v.w - __uint_as_float(e7 & 0xFFFF0000u);

    uint4 mi;
    __nv_bfloat162 t;
    t = __floats2bfloat162_rn(m0, m1); mi.x = *(uint32_t*)&t;
    t = __floats2bfloat162_rn(m2, m3); mi.y = *(uint32_t*)&t;
    t = __floats2bfloat162_rn(m4, m5); mi.z = *(uint32_t*)&t;
    t = __floats2bfloat162_rn(m6, m7); mi.w = *(uint32_t*)&t;

    *(uint4*)hiP = hi;
    *(uint4*)miP = mi;
}

// ---------------- transpose 1024x1024 ---------------------------------------
__global__ void transpose1024(const float* __restrict__ in, float* __restrict__ out)
{
    __shared__ float tile[32][33];
    const int x = blockIdx.x*32 + threadIdx.x;
    const int y = blockIdx.y*32 + threadIdx.y;
    #pragma unroll
    for (int j = 0; j < 32; j += 8)
        tile[threadIdx.y + j][threadIdx.x] = in[(size_t)(y + j)*EE + x];
    __syncthreads();
    const int x2 = blockIdx.y*32 + threadIdx.x;
    const int y2 = blockIdx.x*32 + threadIdx.y;
    #pragma unroll
    for (int j = 0; j < 32; j += 8)
        out[(size_t)(y2 + j)*EE + x2] = tile[threadIdx.x][threadIdx.y + j];
}

// ---------------- prep_v -----------------------------------------------------
__global__ void prep_v(const float* __restrict__ W2,
                       const float* __restrict__ b2,
                       const float* __restrict__ watt)
{
    int hh = blockIdx.x;
    int d  = threadIdx.x;
    const float* row = W2 + ((size_t)hh*DD + d)*EE;
    float a0=0.f,a1=0.f,a2=0.f,a3=0.f;
    for (int e = 0; e < EE; e += 4) {
        a0 = fmaf(row[e+0], watt[e+0], a0);
        a1 = fmaf(row[e+1], watt[e+1], a1);
        a2 = fmaf(row[e+2], watt[e+2], a2);
        a3 = fmaf(row[e+3], watt[e+3], a3);
    }
    g_V[hh*DD + d] = (a0+a1)+(a2+a3);
    if (d == 0) {
        const float* br = b2 + (size_t)hh*EE;
        float c0=0.f;
        for (int e = 0; e < EE; e++) c0 = fmaf(br[e], watt[e], c0);
        g_C[hh] = c0;
    }
}

// ======= split-bf16 3-pass GEMM via mma.m16n8k16 + ldmatrix ==================
// A [8192,1024] fp32 row-major, Bt [1024][1024] fp32 (W^T rows of k).
// CTA 128x128, 8 warps (2m x 4n), warp tile 64x32; k-chunk 16; double-buffered.
// smem per stage: A_hi, A_mid, B_hi, B_mid planes of 128 rows x 16 bf16,
// row stride 48B (conflict-free for ldmatrix: offsets mod 128B all distinct).
// EPI==0: g_Z = tanh(v + bias[c]); EPI==2: g_P = v + sum_h g_SC[r][h]*bias[h*1024+c]
#define PL   6144           // plane bytes (128 * 48)
#define STG  (4*PL)         // stage bytes  (24576)
template<int EPI>
__global__ void __launch_bounds__(256, 2) bf_gemm(
    const float* __restrict__ Aext, const float* __restrict__ Bt,
    const float* __restrict__ bias)
{
    extern __shared__ char smq[];   // 2 * STG = 49152 bytes
    const float* A = (EPI==0) ? Aext : g_G;
    float*       C = (EPI==0) ? g_Z  : g_P;

    const int tid  = threadIdx.x;
    const int wid  = tid >> 5;
    const int lane = tid & 31;
    const int wm   = wid >> 2;      // 0..1
    const int wn   = wid & 3;       // 0..3
    const int rr   = lane & 7;
    const int mq   = lane >> 3;     // 0..3
    const int r    = lane >> 2;     // 0..7
    const int cq   = lane & 3;      // 0..3

    const int m0 = blockIdx.y * 128;
    const int n0 = blockIdx.x * 128;

    // producer mapping: thread -> (row 0..127, half 0/1 of 16 k's)
    const int prow = tid >> 1;
    const int phalf = tid & 1;
    const float* srcA = A  + (size_t)(m0 + prow)*EE + phalf*8;
    const float* srcB = Bt + (size_t)(n0 + prow)*EE + phalf*8;
    char* pdst = smq + prow*48 + phalf*16;

    // consumer ldmatrix lane addresses (within stage)
    const uint32_t sb = smem_u32(smq);
    const uint32_t aAddr = sb + (uint32_t)((wm*64 + (mq&1)*8 + rr)*48 + (mq>>1)*16);
    const uint32_t bAddr = sb + 2u*PL + (uint32_t)((wn*32 + rr)*48 + (mq&1)*16);

    // prologue: chunk 0
    {
        float4 a0 = *(const float4*)(srcA);
        float4 a1 = *(const float4*)(srcA + 4);
        float4 b0 = *(const float4*)(srcB);
        float4 b1 = *(const float4*)(srcB + 4);
        split_store8(a0, a1, pdst,        pdst + PL);
        split_store8(b0, b1, pdst + 2*PL, pdst + 3*PL);
    }
    __syncthreads();

    float acc[4][4][4];
    #pragma unroll
    for (int i = 0; i < 4; i++)
        #pragma unroll
        for (int j = 0; j < 4; j++)
            #pragma unroll
            for (int q = 0; q < 4; q++) acc[i][j][q] = 0.f;

    const int NKT = EE / 16;   // 64
    #pragma unroll 1
    for (int kt = 0; kt < NKT; kt++) {
        float4 pa0, pa1, pb0, pb1;
        if (kt + 1 < NKT) {
            const int ko = (kt + 1) * 16;
            pa0 = *(const float4*)(srcA + ko);
            pa1 = *(const float4*)(srcA + ko + 4);
            pb0 = *(const float4*)(srcB + ko);
            pb1 = *(const float4*)(srcB + ko + 4);
        }

        const uint32_t st = (kt & 1) * (uint32_t)STG;

        // B fragments (hi + mid planes), 4 n-tiles
        uint32_t bh[4][2], bm[4][2];
        #pragma unroll
        for (int ni = 0; ni < 4; ni++) {
            LDSM2(bh[ni][0], bh[ni][1], bAddr + st + ni*384);
            LDSM2(bm[ni][0], bm[ni][1], bAddr + st + PL + ni*384);
        }

        #pragma unroll
        for (int mi = 0; mi < 4; mi++) {
            uint32_t ah[4], am[4];
            LDSM4(ah[0], ah[1], ah[2], ah[3], aAddr + st + mi*768);
            LDSM4(am[0], am[1], am[2], am[3], aAddr + st + PL + mi*768);
            #pragma unroll
            for (int ni = 0; ni < 4; ni++) mmabf(acc[mi][ni], ah, bh[ni]);
            #pragma unroll
            for (int ni = 0; ni < 4; ni++) mmabf(acc[mi][ni], ah, bm[ni]);
            #pragma unroll
            for (int ni = 0; ni < 4; ni++) mmabf(acc[mi][ni], am, bh[ni]);
        }

        if (kt + 1 < NKT) {
            char* nd = pdst + (((kt + 1) & 1) ? STG : 0);
            split_store8(pa0, pa1, nd,        nd + PL);
            split_store8(pb0, pb1, nd + 2*PL, nd + 3*PL);
        }
        __syncthreads();
    }

    // ---------------- epilogue ----------------
    #pragma unroll
    for (int mi = 0; mi < 4; mi++) {
        const int row0 = m0 + wm*64 + mi*16 + r;    // and row0+8
        float sAr[8], sBr[8];
        if (EPI == 2) {
            #pragma unroll
            for (int h2 = 0; h2 < 8; h2++) {
                sAr[h2] = g_SC[(size_t)row0*8 + h2];
                sBr[h2] = g_SC[(size_t)(row0+8)*8 + h2];
            }
        }
        #pragma unroll
        for (int ni = 0; ni < 4; ni++) {
            const int col = n0 + wn*32 + ni*8 + 2*cq;
            float v0 = acc[mi][ni][0], v1 = acc[mi][ni][1];
            float v2 = acc[mi][ni][2], v3 = acc[mi][ni][3];
            if (EPI == 0) {
                v0 = tanhf(v0 + bias[col]);
                v1 = tanhf(v1 + bias[col+1]);
                v2 = tanhf(v2 + bias[col]);
                v3 = tanhf(v3 + bias[col+1]);
            } else {
                float b00=0.f, b01=0.f, b10=0.f, b11=0.f;
                #pragma unroll
                for (int h2 = 0; h2 < 8; h2++) {
                    const float w0 = bias[(size_t)h2*EE + col];
                    const float w1 = bias[(size_t)h2*EE + col + 1];
                    b00 = fmaf(sAr[h2], w0, b00);
                    b01 = fmaf(sAr[h2], w1, b01);
                    b10 = fmaf(sBr[h2], w0, b10);
                    b11 = fmaf(sBr[h2], w1, b11);
                }
                v0 += b00; v1 += b01; v2 += b10; v3 += b11;
            }
            float2 p0; p0.x = v0; p0.y = v1;
            float2 p1; p1.x = v2; p1.y = v3;
            *(float2*)(C + (size_t)row0*EE + col)     = p0;
            *(float2*)(C + (size_t)(row0+8)*EE + col) = p1;
        }
    }
}

// ---------------- SIMT 128x128 GEMM for per-head FFN ------------------------
__global__ void __launch_bounds__(256, 2) gemm_ffn(
    const float* __restrict__ Bm, const float* __restrict__ bias)
{
    const float* A = g_HLN;
    float*       C = g_H1;

    __shared__ float As[2][8][128];
    __shared__ float Bs[2][8][128];

    const int tid = threadIdx.x;
    const int by  = blockIdx.y;
    const int h   = blockIdx.z;

    const int tx = tid & 15;
    const int ty = tid >> 4;
    const int arow = tid >> 1;
    const int ac4  = (tid & 1) * 4;
    const int brow = tid >> 5;
    const int bc4  = (tid & 31) * 4;

    const float* Ag = A + (size_t)h*DD + (size_t)(by*128 + arow)*1024 + ac4;
    const float* Bg = Bm + (size_t)h*DD*DD + (size_t)brow*DD + bc4;

    float4 ar = *(const float4*)Ag;
    float4 br = *(const float4*)Bg;

    As[0][ac4+0][arow] = ar.x;
    As[0][ac4+1][arow] = ar.y;
    As[0][ac4+2][arow] = ar.z;
    As[0][ac4+3][arow] = ar.w;
    *(float4*)&Bs[0][brow][bc4] = br;
    __syncthreads();

    float acc[8][8];
    #pragma unroll
    for (int i = 0; i < 8; i++)
        #pragma unroll
        for (int j = 0; j < 8; j++) acc[i][j] = 0.f;

    const int nk = DD >> 3;   // 16
    for (int kt = 0; kt < nk; kt++) {
        const int cur = kt & 1;
        const int nxt = cur ^ 1;
        if (kt + 1 < nk) {
            ar = *(const float4*)(Ag + (size_t)(kt+1)*8);
            br = *(const float4*)(Bg + (size_t)(kt+1)*8*DD);
        }
        #pragma unroll
        for (int k = 0; k < 8; k++) {
            float a[8], b[8];
            *(float4*)(a)   = *(float4*)&As[cur][k][ty*8];
            *(float4*)(a+4) = *(float4*)&As[cur][k][ty*8+4];
            *(float4*)(b)   = *(float4*)&Bs[cur][k][tx*8];
            *(float4*)(b+4) = *(float4*)&Bs[cur][k][tx*8+4];
            #pragma unroll
            for (int i = 0; i < 8; i++)
                #pragma unroll
                for (int j = 0; j < 8; j++)
                    acc[i][j] = fmaf(a[i], b[j], acc[i][j]);
        }
        if (kt + 1 < nk) {
            As[nxt][ac4+0][arow] = ar.x;
            As[nxt][ac4+1][arow] = ar.y;
            As[nxt][ac4+2][arow] = ar.z;
            As[nxt][ac4+3][arow] = ar.w;
            *(float4*)&Bs[nxt][brow][bc4] = br;
        }
        __syncthreads();
    }

    const int colBase = h*DD;
    const int rBase   = by*128 + ty*8;
    #pragma unroll
    for (int i = 0; i < 8; i++) {
        const int r = rBase + i;
        float logit = 0.f;
        #pragma unroll
        for (int j = 0; j < 8; j++) {
            const int c = colBase + tx*8 + j;
            float v = acc[i][j] + bias[c];
            v = 0.5f * v * (1.f + erff(v * 0.70710678118654752f));
            logit = fmaf(v, g_V[c], logit);
            C[(size_t)r*1024 + c] = v;
        }
        #pragma unroll
        for (int off = 8; off >= 1; off >>= 1)
            logit += __shfl_xor_sync(0xffffffffu, logit, off);
        if (tx == 0) g_LG[(size_t)r*8 + h] = logit + g_C[h];
    }
}

// ---------------- sequential gated scan + per-step LN -----------------------
__global__ void scan_kernel(const float* __restrict__ Uh,
                            const float* __restrict__ Uz,
                            const float* __restrict__ Bu,
                            const float* __restrict__ Lg,
                            const float* __restrict__ Lb)
{
    const int bidx = blockIdx.x;
    const int b  = bidx >> 3;
    const int hh = bidx & 7;
    const int lane = threadIdx.x;

    float uh[4], uz[4], bu[4], lg[4], lb[4], h[4];
    #pragma unroll
    for (int i = 0; i < 4; i++) {
        const int d = lane + 32*i;
        uh[i] = Uh[(size_t)hh*DD*DD + (size_t)d*(DD+1)];
        uz[i] = Uz[(size_t)hh*DD*DD + (size_t)d*(DD+1)];
        bu[i] = Bu[hh*DD + d];
        lg[i] = Lg[d];
        lb[i] = Lb[d];
        h[i]  = 0.f;
    }

    const float* zp = g_Z  + (size_t)b*SS*EE + hh*DD + lane;
    float*       sp = g_ST + (size_t)b*SS*EE + hh*DD + lane;

    float z0[4], z1[4];
    #pragma unroll
    for (int i = 0; i < 4; i++) z0[i] = zp[32*i];
    #pragma unroll
    for (int i = 0; i < 4; i++) z1[i] = zp[1024 + 32*i];

    for (int s = 0; s < SS; s++) {
        float z2[4] = {0.f, 0.f, 0.f, 0.f};
        if (s + 2 < SS) {
            const float* p = zp + (size_t)(s+2)*EE;
            #pragma unroll
            for (int i = 0; i < 4; i++) z2[i] = p[32*i];
        }
        float hn[4];
        float s1 = 0.f, s2 = 0.f;
        #pragma unroll
        for (int i = 0; i < 4; i++) {
            float t = fmaf(h[i], uh[i], fmaf(z0[i], uz[i], bu[i]));
            float u = __fdividef(1.f, 1.f + __expf(-t));
            float v = fmaf(u, h[i] - z0[i], z0[i]);
            hn[i] = v;
            s1 += v;
            s2 = fmaf(v, v, s2);
        }
        #pragma unroll
        for (int off = 16; off >= 1; off >>= 1) {
            s1 += __shfl_xor_sync(0xffffffffu, s1, off);
            s2 += __shfl_xor_sync(0xffffffffu, s2, off);
        }
        const float mean = s1 * (1.f/128.f);
        const float var  = fmaf(s2, 1.f/128.f, -mean*mean);
        const float rstd = rsqrtf(var + EPSF);
        float* so = sp + (size_t)s*EE;
        #pragma unroll
        for (int i = 0; i < 4; i++) {
            float o = fmaf((hn[i] - mean) * rstd, lg[i], lb[i]);
            h[i] = o;
            so[32*i] = o;
        }
        #pragma unroll
        for (int i = 0; i < 4; i++) { z0[i] = z1[i]; z1[i] = z2[i]; }
    }
}

// ---------------- head_ln ----------------------------------------------------
__global__ void head_ln(const float* __restrict__ OS,
                        const float* __restrict__ fg,
                        const float* __restrict__ fb)
{
    const int r    = blockIdx.x*8 + (threadIdx.x >> 5);
    const int lane = threadIdx.x & 31;
    const int hh   = r & 7;

    const float4 v = ((const float4*)(g_ST + (size_t)r*128))[lane];
    const int d0 = lane*4;
    const float* osb = OS + (size_t)hh*DD*DD;
    const float o0 = osb[(size_t)(d0+0)*(DD+1)];
    const float o1 = osb[(size_t)(d0+1)*(DD+1)];
    const float o2 = osb[(size_t)(d0+2)*(DD+1)];
    const float o3 = osb[(size_t)(d0+3)*(DD+1)];
    const float y0 = v.x*o0, y1 = v.y*o1, y2 = v.z*o2, y3 = v.w*o3;

    float s1 = (y0+y1)+(y2+y3);
    float s2 = fmaf(y0,y0, fmaf(y1,y1, fmaf(y2,y2, y3*y3)));
    #pragma unroll
    for (int off = 16; off >= 1; off >>= 1) {
        s1 += __shfl_xor_sync(0xffffffffu, s1, off);
        s2 += __shfl_xor_sync(0xffffffffu, s2, off);
    }
    const float mean = s1 * (1.f/128.f);
    const float var  = fmaf(s2, 1.f/128.f, -mean*mean);
    const float rstd = rsqrtf(var + EPSF);

    const float4 gv = ((const float4*)(fg + hh*128))[lane];
    const float4 bv = ((const float4*)(fb + hh*128))[lane];
    float4 o;
    o.x = fmaf((y0-mean)*rstd, gv.x, bv.x);
    o.y = fmaf((y1-mean)*rstd, gv.y, bv.y);
    o.z = fmaf((y2-mean)*rstd, gv.z, bv.z);
    o.w = fmaf((y3-mean)*rstd, gv.w, bv.w);
    ((float4*)(g_HLN + (size_t)r*128))[lane] = o;
}

// ---------------- softmax over heads + scale h1 -> g ------------------------
__global__ void softmax_scale()
{
    const int t    = blockIdx.x*8 + (threadIdx.x >> 5);
    const int lane = threadIdx.x & 31;

    float l[8];
    #pragma unroll
    for (int h2 = 0; h2 < 8; h2++) l[h2] = g_LG[(size_t)t*8 + h2];
    float m = l[0];
    #pragma unroll
    for (int h2 = 1; h2 < 8; h2++) m = fmaxf(m, l[h2]);
    float ssum = 0.f;
    #pragma unroll
    for (int h2 = 0; h2 < 8; h2++) { l[h2] = __expf(l[h2]-m); ssum += l[h2]; }
    const float inv = __fdividef(1.f, ssum);

    const float4* in  = (const float4*)(g_H1 + (size_t)t*1024);
    float4*       out = (float4*)      (g_G  + (size_t)t*1024);
    #pragma unroll
    for (int i = 0; i < 8; i++) {
        const float sh = l[i]*inv;
        float4 v = in[i*32 + lane];
        v.x *= sh; v.y *= sh; v.z *= sh; v.w *= sh;
        out[i*32 + lane] = v;
    }
    if (lane < 8) g_SC[(size_t)t*8 + lane] = l[lane]*inv;
}

// ---------------- final LN over E -------------------------------------------
__global__ void final_ln(const float* __restrict__ lg_,
                         const float* __restrict__ lb_,
                         float* __restrict__ out)
{
    __shared__ float sm[16];
    const int t   = blockIdx.x;
    const int tid = threadIdx.x;

    const float4 v = ((const float4*)(g_P + (size_t)t*1024))[tid];
    float s1 = (v.x+v.y)+(v.z+v.w);
    float s2 = fmaf(v.x,v.x, fmaf(v.y,v.y, fmaf(v.z,v.z, v.w*v.w)));
    #pragma unroll
    for (int off = 16; off >= 1; off >>= 1) {
        s1 += __shfl_xor_sync(0xffffffffu, s1, off);
        s2 += __shfl_xor_sync(0xffffffffu, s2, off);
    }
    const int w = tid >> 5, lane = tid & 31;
    if (lane == 0) { sm[w] = s1; sm[8+w] = s2; }
    __syncthreads();
    float t1 = 0.f, t2 = 0.f;
    #pragma unroll
    for (int w2 = 0; w2 < 8; w2++) { t1 += sm[w2]; t2 += sm[8+w2]; }
    const float mean = t1 * (1.f/1024.f);
    const float var  = fmaf(t2, 1.f/1024.f, -mean*mean);
    const float rstd = rsqrtf(var + EPSF);

    const float4 g4 = ((const float4*)lg_)[tid];
    const float4 b4 = ((const float4*)lb_)[tid];
    float4 o;
    o.x = fmaf((v.x-mean)*rstd, g4.x, b4.x);
    o.y = fmaf((v.y-mean)*rstd, g4.y, b4.y);
    o.z = fmaf((v.z-mean)*rstd, g4.z, b4.z);
    o.w = fmaf((v.w-mean)*rstd, g4.w, b4.w);
    ((float4*)(out + (size_t)t*1024))[tid] = o;
}

// ---------------- launch ----------------------------------------------------
#define GEMM_SMEM (2*STG)   // 49152 bytes

extern "C" void kernel_launch(void* const* d_in, const int* in_sizes, int n_in,
                              void* d_out, int out_size)
{
    const float* x      = (const float*)d_in[0];
    const float* W_ez   = (const float*)d_in[1];
    const float* b_ez   = (const float*)d_in[2];
    const float* U_h    = (const float*)d_in[3];
    const float* U_z    = (const float*)d_in[4];
    const float* b_u    = (const float*)d_in[5];
    const float* out_sh = (const float*)d_in[6];
    const float* lns_g  = (const float*)d_in[7];
    const float* lns_b  = (const float*)d_in[8];
    const float* ffln_g = (const float*)d_in[9];
    const float* ffln_b = (const float*)d_in[10];
    const float* ff_W1  = (const float*)d_in[11];
    const float* ff_b1  = (const float*)d_in[12];
    const float* ff_W2  = (const float*)d_in[13];
    const float* ff_b2  = (const float*)d_in[14];
    const float* w_att  = (const float*)d_in[15];
    // d_in[16] = b_att: cancels in softmax
    const float* lno_g  = (const float*)d_in[17];
    const float* lno_b  = (const float*)d_in[18];
    float* out = (float*)d_out;

    cudaFuncSetAttribute(bf_gemm<0>, cudaFuncAttributeMaxDynamicSharedMemorySize, GEMM_SMEM);
    cudaFuncSetAttribute(bf_gemm<2>, cudaFuncAttributeMaxDynamicSharedMemorySize, GEMM_SMEM);

    float* wezT; cudaGetSymbolAddress((void**)&wezT, g_WezT);
    float* w2T;  cudaGetSymbolAddress((void**)&w2T,  g_W2T);

    // prep (independent)
    transpose1024<<<dim3(32,32), dim3(32,8)>>>(W_ez, wezT);
    transpose1024<<<dim3(32,32), dim3(32,8)>>>(ff_W2, w2T);
    prep_v<<<HH, DD>>>(ff_W2, ff_b2, w_att);

    // z = tanh(x @ W_ez + b_ez)   [split-bf16 3-pass mma]
    bf_gemm<0><<<dim3(EE/128, TT/128), 256, GEMM_SMEM>>>(x, wezT, b_ez);

    // sequential gated scan with per-step LN
    scan_kernel<<<BB*HH, 32>>>(U_h, U_z, b_u, lns_g, lns_b);

    // hln = LN(states * os_diag)
    head_ln<<<TT*HH/8, 256>>>(out_sh, ffln_g, ffln_b);

    // h1 = gelu(hln @ W1[h] + b1[h]); logits in epilogue  [SIMT]
    gemm_ffn<<<dim3(1, TT/128, HH), 256>>>(ff_W1, ff_b1);

    // softmax over heads; g = score * h1
    softmax_scale<<<TT/8, 256>>>();

    // weighted = g @ W2 + sum_h s_h*b2   [split-bf16 3-pass mma]
    bf_gemm<2><<<dim3(EE/128, TT/128), 256, GEMM_SMEM>>>(nullptr, w2T, ff_b2);

    // final LN -> output
    final_ln<<<TT, 256>>>(lno_g, lno_b, out);
}